// round 1
// baseline (speedup 1.0000x reference)
#include <cuda_runtime.h>

// Problem constants: B=4, C=64, T=8, H=32, W=32, O=64
#define B_   4
#define TT_  8
#define N_   32          // B*T
#define C_   64
#define HW   1024        // H*W
#define CHW  65536       // C*HW

// ---------------- scratch (device globals; no allocation) ----------------
__device__ float g_rq[N_*C_*HW];               // 8 MB   (n,c,i) relu(q)
__device__ float g_rk[N_*C_*HW];               // 8 MB
__device__ float g_rv[N_*C_*HW];               // 8 MB
__device__ float g_gc[N_*C_*C_];               // 512 KB channel scores / softmaxed
__device__ float g_ms[(size_t)N_*HW*HW];       // 128 MB spatial scores / softmaxed
__device__ float g_s [N_*C_*HW];               // 8 MB   a_c + a_s
__device__ float g_xe[N_*C_*HW];               // 8 MB   relu(tconv3)
__device__ float g_mt[B_*TT_*TT_];             // temporal scores

// ---------------- K1: q/k/v = relu(W x + b), layout (n,c,i) ----------------
__global__ __launch_bounds__(256) void k_qkv(
    const float* __restrict__ x,
    const float* __restrict__ wq, const float* __restrict__ bq,
    const float* __restrict__ wk, const float* __restrict__ bk,
    const float* __restrict__ wv, const float* __restrict__ bv)
{
    int n = blockIdx.x;
    int b = n >> 3, t = n & 7;
    int i = (blockIdx.y << 8) + threadIdx.x;

    // x[b][c][t][i], c-stride = T*HW
    const float* xp = x + ((size_t)b * C_ * TT_ + t) * HW + i;
    float xr[C_];
#pragma unroll
    for (int c = 0; c < C_; c++) xr[c] = xp[(size_t)c * TT_ * HW];

    __shared__ float sw[C_*C_];
    __shared__ float sb[C_];

    for (int p = 0; p < 3; p++) {
        const float* W  = (p == 0) ? wq : (p == 1) ? wk : wv;
        const float* Bb = (p == 0) ? bq : (p == 1) ? bk : bv;
        float*       Op = (p == 0) ? g_rq : (p == 1) ? g_rk : g_rv;
        __syncthreads();
        for (int k = threadIdx.x; k < C_*C_; k += 256) sw[k] = W[k];
        if (threadIdx.x < C_) sb[threadIdx.x] = Bb[threadIdx.x];
        __syncthreads();
        float* op = Op + (n * C_) * HW + i;
        for (int o = 0; o < C_; o++) {
            float acc = sb[o];
#pragma unroll
            for (int c = 0; c < C_; c++) acc = fmaf(sw[o*C_ + c], xr[c], acc);
            op[o * HW] = fmaxf(acc, 0.f);
        }
    }
}

// ---------------- K2: channel scores G[n][c][d] = sum_i q[n,c,i] k[n,d,i] ----------------
__global__ __launch_bounds__(256) void k_gc()
{
    int n = blockIdx.x;
    __shared__ float sq[C_*65];   // padded stride 65
    __shared__ float sk[C_*65];
    int tid = threadIdx.x;
    int ty = tid >> 4, tx = tid & 15;

    float acc[4][4];
#pragma unroll
    for (int r = 0; r < 4; r++)
#pragma unroll
        for (int s2 = 0; s2 < 4; s2++) acc[r][s2] = 0.f;

    for (int it = 0; it < 16; it++) {
        __syncthreads();
        for (int k = tid; k < C_*64; k += 256) {
            int c = k >> 6, ii = k & 63;
            sq[c*65 + ii] = g_rq[(n*C_ + c)*HW + it*64 + ii];
            sk[c*65 + ii] = g_rk[(n*C_ + c)*HW + it*64 + ii];
        }
        __syncthreads();
        for (int ii = 0; ii < 64; ii++) {
            float a[4], bb[4];
#pragma unroll
            for (int r = 0; r < 4; r++)  a[r]  = sq[(ty*4 + r)*65 + ii];
#pragma unroll
            for (int s2 = 0; s2 < 4; s2++) bb[s2] = sk[(tx*4 + s2)*65 + ii];
#pragma unroll
            for (int r = 0; r < 4; r++)
#pragma unroll
                for (int s2 = 0; s2 < 4; s2++) acc[r][s2] = fmaf(a[r], bb[s2], acc[r][s2]);
        }
    }
#pragma unroll
    for (int r = 0; r < 4; r++)
#pragma unroll
        for (int s2 = 0; s2 < 4; s2++)
            g_gc[n*C_*C_ + (ty*4 + r)*C_ + tx*4 + s2] = acc[r][s2];
}

// ---------------- K3a: softmax over n of G (axis 0) ----------------
__global__ void k_gc_softmax()
{
    int cd = blockIdx.x * 256 + threadIdx.x;   // 0..4095
    float v[N_];
    float mx = -1e30f;
#pragma unroll
    for (int n = 0; n < N_; n++) { v[n] = g_gc[n*4096 + cd]; mx = fmaxf(mx, v[n]); }
    float s = 0.f;
#pragma unroll
    for (int n = 0; n < N_; n++) { v[n] = __expf(v[n] - mx); s += v[n]; }
    float inv = 1.f / s;
#pragma unroll
    for (int n = 0; n < N_; n++) g_gc[n*4096 + cd] = v[n] * inv;
}

// ---------------- K3b: a_c[n,c,i] = sum_d m_c[n,c,d] v[n,d,i] -> g_s ----------------
__global__ __launch_bounds__(256) void k_ac()
{
    int n = blockIdx.x;
    int i = (blockIdx.y << 8) + threadIdx.x;
    __shared__ float sm[C_*C_];
    for (int k = threadIdx.x; k < C_*C_; k += 256) sm[k] = g_gc[n*4096 + k];
    __syncthreads();
    float vr[C_];
#pragma unroll
    for (int d = 0; d < C_; d++) vr[d] = g_rv[(n*C_ + d)*HW + i];
    for (int c = 0; c < C_; c++) {
        float acc = 0.f;
#pragma unroll
        for (int d = 0; d < C_; d++) acc = fmaf(sm[c*C_ + d], vr[d], acc);
        g_s[(n*C_ + c)*HW + i] = acc;
    }
}

// ---------------- K4: spatial scores m_s[n,i,j] = sum_c q[n,c,i] k[n,c,j] ----------------
__global__ __launch_bounds__(256) void k_ms()
{
    int n  = blockIdx.z;
    int i0 = blockIdx.x << 6, j0 = blockIdx.y << 6;
    __shared__ float sa[64*64];
    __shared__ float sbm[64*64];
    int tid = threadIdx.x, ty = tid >> 4, tx = tid & 15;

    for (int k = tid; k < 4096; k += 256) {
        int c = k >> 6, ii = k & 63;
        sa [k] = g_rq[(n*C_ + c)*HW + i0 + ii];
        sbm[k] = g_rk[(n*C_ + c)*HW + j0 + ii];
    }
    __syncthreads();

    float acc[4][4];
#pragma unroll
    for (int r = 0; r < 4; r++)
#pragma unroll
        for (int s2 = 0; s2 < 4; s2++) acc[r][s2] = 0.f;

#pragma unroll
    for (int c = 0; c < 64; c++) {
        float4 av = *(const float4*)&sa [c*64 + ty*4];
        float4 bv = *(const float4*)&sbm[c*64 + tx*4];
        float aa[4] = {av.x, av.y, av.z, av.w};
        float bb[4] = {bv.x, bv.y, bv.z, bv.w};
#pragma unroll
        for (int r = 0; r < 4; r++)
#pragma unroll
            for (int s2 = 0; s2 < 4; s2++) acc[r][s2] = fmaf(aa[r], bb[s2], acc[r][s2]);
    }

    float* outp = g_ms + ((size_t)n << 20);
#pragma unroll
    for (int r = 0; r < 4; r++) {
        float4 o4 = make_float4(acc[r][0], acc[r][1], acc[r][2], acc[r][3]);
        *(float4*)&outp[(i0 + ty*4 + r)*HW + j0 + tx*4] = o4;
    }
}

// ---------------- K5: softmax over n of m_s (axis 0) ----------------
__global__ void k_ms_softmax()
{
    int ij = blockIdx.x * 256 + threadIdx.x;   // 0..(HW*HW-1)
    float v[N_];
    float mx = -1e30f;
#pragma unroll
    for (int n = 0; n < N_; n++) { v[n] = g_ms[((size_t)n << 20) + ij]; mx = fmaxf(mx, v[n]); }
    float s = 0.f;
#pragma unroll
    for (int n = 0; n < N_; n++) { v[n] = __expf(v[n] - mx); s += v[n]; }
    float inv = 1.f / s;
#pragma unroll
    for (int n = 0; n < N_; n++) g_ms[((size_t)n << 20) + ij] = v[n] * inv;
}

// ---------------- K6: a_s[n,c,i] = sum_j m_s[n,i,j] v[n,c,j]; g_s += a_s ----------------
__global__ __launch_bounds__(256) void k_as()
{
    int n  = blockIdx.y;
    int i0 = blockIdx.x << 6;
    __shared__ float sv [64*64];       // v[c][j]
    __shared__ float smt[64*68];       // m^T[j][i], padded stride 68 (float4-aligned)
    int tid = threadIdx.x, ty = tid >> 4, tx = tid & 15;

    float acc[4][4];
#pragma unroll
    for (int r = 0; r < 4; r++)
#pragma unroll
        for (int s2 = 0; s2 < 4; s2++) acc[r][s2] = 0.f;

    const float* msp = g_ms + ((size_t)n << 20);
    for (int jt = 0; jt < 16; jt++) {
        int j0 = jt << 6;
        __syncthreads();
        for (int k = tid; k < 4096; k += 256) {
            int row = k >> 6, jj = k & 63;
            sv[k] = g_rv[(n*C_ + row)*HW + j0 + jj];            // row = c
            smt[jj*68 + row] = msp[(i0 + row)*HW + j0 + jj];    // row = i (transpose in smem)
        }
        __syncthreads();
#pragma unroll
        for (int j = 0; j < 64; j++) {
            float aa[4];
#pragma unroll
            for (int r = 0; r < 4; r++) aa[r] = sv[(ty*4 + r)*64 + j];
            float4 b4 = *(const float4*)&smt[j*68 + tx*4];
            float bb[4] = {b4.x, b4.y, b4.z, b4.w};
#pragma unroll
            for (int r = 0; r < 4; r++)
#pragma unroll
                for (int s2 = 0; s2 < 4; s2++) acc[r][s2] = fmaf(aa[r], bb[s2], acc[r][s2]);
        }
    }
    // accumulate onto a_c already in g_s
#pragma unroll
    for (int r = 0; r < 4; r++) {
        int c = ty*4 + r;
        float4* p = (float4*)&g_s[(n*C_ + c)*HW + i0 + tx*4];
        float4 old = *p;
        old.x += acc[r][0]; old.y += acc[r][1]; old.z += acc[r][2]; old.w += acc[r][3];
        *p = old;
    }
}

// ---------------- K7: Xe = relu(tconv3(s)) : (3,1,1) kernel, pad 1 on t ----------------
__global__ __launch_bounds__(256) void k_tconv(const float* __restrict__ wX,
                                               const float* __restrict__ bX)
{
    int n = blockIdx.x;
    int b = n >> 3, t = n & 7;
    int i = (blockIdx.y << 8) + threadIdx.x;
    __shared__ float sw[32*64];

    for (int h = 0; h < 2; h++) {
        float acc[32];
#pragma unroll
        for (int o = 0; o < 32; o++) acc[o] = bX[h*32 + o];
        for (int kt = 0; kt < 3; kt++) {
            int t2 = t + kt - 1;
            __syncthreads();
            for (int k = threadIdx.x; k < 2048; k += 256) {
                int o = k >> 6, c = k & 63;
                sw[k] = wX[((h*32 + o)*64 + c)*3 + kt];
            }
            __syncthreads();
            if (t2 < 0 || t2 >= TT_) continue;   // uniform per block
            float xr[64];
#pragma unroll
            for (int c = 0; c < 64; c++) xr[c] = g_s[((b*TT_ + t2)*C_ + c)*HW + i];
            for (int o = 0; o < 32; o++) {
                float a = acc[o];
#pragma unroll
                for (int c = 0; c < 64; c++) a = fmaf(sw[o*64 + c], xr[c], a);
                acc[o] = a;
            }
        }
        for (int o = 0; o < 32; o++)
            g_xe[(n*C_ + h*32 + o)*HW + i] = fmaxf(acc[o], 0.f);
        __syncthreads();
    }
}

// ---------------- K8a: temporal scores m_t[b,t,s] = <Xe[b,t,:], Xe[b,s,:]> ----------------
__global__ void k_mt()
{
    int idx = blockIdx.x;            // b*64 + t*8 + s
    int b = idx >> 6, ts = idx & 63;
    int t = ts >> 3, s2 = ts & 7;
    const float* qp = g_xe + (size_t)(b*TT_ + t)  * CHW;
    const float* kp = g_xe + (size_t)(b*TT_ + s2) * CHW;
    float sum = 0.f;
    for (int d = threadIdx.x; d < CHW; d += 256) sum = fmaf(qp[d], kp[d], sum);
    __shared__ float red[256];
    red[threadIdx.x] = sum;
    __syncthreads();
    for (int off = 128; off > 0; off >>= 1) {
        if (threadIdx.x < off) red[threadIdx.x] += red[threadIdx.x + off];
        __syncthreads();
    }
    if (threadIdx.x == 0) g_mt[idx] = red[0];
}

// ---------------- K8b: softmax over b (axis 0) of m_t ----------------
__global__ void k_mt_softmax()
{
    int ts = threadIdx.x;  // 0..63
    float v[B_];
    float mx = -1e30f;
#pragma unroll
    for (int b = 0; b < B_; b++) { v[b] = g_mt[b*64 + ts]; mx = fmaxf(mx, v[b]); }
    float s = 0.f;
#pragma unroll
    for (int b = 0; b < B_; b++) { v[b] = __expf(v[b] - mx); s += v[b]; }
    float inv = 1.f / s;
#pragma unroll
    for (int b = 0; b < B_; b++) g_mt[b*64 + ts] = v[b] * inv;
}

// ---------------- K8c: out[b,c,t,i] = sum_s m_t[b,t,s] v[(b,s),c,i] ----------------
__global__ __launch_bounds__(256) void k_out(float* __restrict__ out)
{
    int bct = blockIdx.x;            // (b*64+c)*8 + t, 2048 blocks
    int t  = bct & 7;
    int bc = bct >> 3;
    int b  = bc >> 6, c = bc & 63;
    __shared__ float smt[8];
    if (threadIdx.x < 8) smt[threadIdx.x] = g_mt[b*64 + t*8 + threadIdx.x];
    __syncthreads();
    for (int i = threadIdx.x; i < HW; i += 256) {
        float acc = 0.f;
#pragma unroll
        for (int s2 = 0; s2 < 8; s2++)
            acc = fmaf(smt[s2], g_rv[((b*TT_ + s2)*C_ + c)*HW + i], acc);
        out[(size_t)bct * HW + i] = acc;
    }
}

// ---------------- launch ----------------
extern "C" void kernel_launch(void* const* d_in, const int* in_sizes, int n_in,
                              void* d_out, int out_size)
{
    const float* x  = (const float*)d_in[0];
    const float* wq = (const float*)d_in[1];
    const float* bq = (const float*)d_in[2];
    const float* wk = (const float*)d_in[3];
    const float* bk = (const float*)d_in[4];
    const float* wv = (const float*)d_in[5];
    const float* bv = (const float*)d_in[6];
    const float* wX = (const float*)d_in[7];
    const float* bX = (const float*)d_in[8];
    float* out = (float*)d_out;
    (void)in_sizes; (void)n_in; (void)out_size;

    k_qkv<<<dim3(N_, 4), 256>>>(x, wq, bq, wk, bk, wv, bv);
    k_gc<<<N_, 256>>>();
    k_gc_softmax<<<16, 256>>>();
    k_ac<<<dim3(N_, 4), 256>>>();
    k_ms<<<dim3(16, 16, N_), 256>>>();
    k_ms_softmax<<<4096, 256>>>();
    k_as<<<dim3(16, N_), 256>>>();
    k_tconv<<<dim3(N_, 4), 256>>>(wX, bX);
    k_mt<<<256, 256>>>();
    k_mt_softmax<<<1, 64>>>();
    k_out<<<2048, 256>>>(out);
}